// round 1
// baseline (speedup 1.0000x reference)
#include <cuda_runtime.h>
#include <math.h>

// Problem constants
#define BB 8
#define TT 1024
#define CC 768
#define HH 12
#define HD 64
#define MROWS (BB * TT)   // 8192

// Scratch (allocation-free: __device__ globals)
__device__ float g_q[MROWS * CC];
__device__ float g_k[MROWS * CC];
__device__ float g_v[MROWS * CC];
__device__ float g_att[MROWS * CC];

// ---------------------------------------------------------------------------
// Tiled SGEMM: C[M,N] = A[M,K] @ W[K,N] + bias[N]
// BM=BN=64, BK=16, 256 threads, 4x4 microtile per thread.
// ---------------------------------------------------------------------------
__global__ __launch_bounds__(256) void gemm_bias_kernel(
    const float* __restrict__ A, const float* __restrict__ W,
    const float* __restrict__ bias, float* __restrict__ C,
    int M, int N, int K)
{
    const int BM = 64, BN = 64, BK = 16;
    __shared__ float As[BK][BM + 1];   // stored transposed [k][m]
    __shared__ float Bs[BK][BN];

    int tid = threadIdx.x;
    int tx = tid & 15;        // 0..15 -> N
    int ty = tid >> 4;        // 0..15 -> M

    int bm = blockIdx.y * BM;
    int bn = blockIdx.x * BN;

    // A tile load mapping: 64 rows x 4 float4  (256 float4, 1 per thread)
    int ar = tid >> 2;              // 0..63
    int ac = (tid & 3) * 4;         // 0,4,8,12
    // B tile load mapping: 16 rows x 16 float4 (256 float4, 1 per thread)
    int br = tid >> 4;              // 0..15
    int bc = (tid & 15) * 4;        // 0..60

    float acc[4][4];
#pragma unroll
    for (int i = 0; i < 4; i++)
#pragma unroll
        for (int j = 0; j < 4; j++) acc[i][j] = 0.0f;

    for (int k0 = 0; k0 < K; k0 += BK) {
        float4 av = *(const float4*)(A + (size_t)(bm + ar) * K + k0 + ac);
        float4 bv = *(const float4*)(W + (size_t)(k0 + br) * N + bn + bc);
        As[ac + 0][ar] = av.x;
        As[ac + 1][ar] = av.y;
        As[ac + 2][ar] = av.z;
        As[ac + 3][ar] = av.w;
        *(float4*)&Bs[br][bc] = bv;
        __syncthreads();

#pragma unroll
        for (int kk = 0; kk < BK; kk++) {
            float a[4], b[4];
#pragma unroll
            for (int i = 0; i < 4; i++) a[i] = As[kk][ty * 4 + i];
            float4 b4 = *(const float4*)&Bs[kk][tx * 4];
            b[0] = b4.x; b[1] = b4.y; b[2] = b4.z; b[3] = b4.w;
#pragma unroll
            for (int i = 0; i < 4; i++)
#pragma unroll
                for (int j = 0; j < 4; j++)
                    acc[i][j] += a[i] * b[j];
        }
        __syncthreads();
    }

#pragma unroll
    for (int i = 0; i < 4; i++) {
        int row = bm + ty * 4 + i;
#pragma unroll
        for (int j = 0; j < 4; j++) {
            int col = bn + tx * 4 + j;
            C[(size_t)row * N + col] = acc[i][j] + bias[col];
        }
    }
}

// ---------------------------------------------------------------------------
// Causal flash attention.
// Q,K,V,O layouts: [B*T, C] with head h occupying cols [h*64, h*64+64).
// grid: (T/32, H, B); block: 256 threads (8 warps x 4 query rows each).
// ---------------------------------------------------------------------------
__global__ __launch_bounds__(256) void attn_kernel(
    const float* __restrict__ Q, const float* __restrict__ K,
    const float* __restrict__ V, float* __restrict__ O)
{
    const int QROWS = 32, KT = 64;
    __shared__ float Qs[QROWS][HD + 1];
    __shared__ float Ks[KT][HD + 1];
    __shared__ float Vs[KT][HD + 1];

    int tid = threadIdx.x;
    int warp = tid >> 5, lane = tid & 31;
    int b = blockIdx.z, h = blockIdx.y;
    int q0 = blockIdx.x * QROWS;
    const float scale = 0.125f;  // 1/sqrt(64)

    const float* Qb = Q + (size_t)(b * TT) * CC + h * HD;
    const float* Kb0 = K + (size_t)(b * TT) * CC + h * HD;
    const float* Vb0 = V + (size_t)(b * TT) * CC + h * HD;

    // load Q tile (32 rows x 64), pre-scaled
    for (int idx = tid; idx < QROWS * (HD / 4); idx += 256) {
        int r = idx >> 4;
        int c = (idx & 15) * 4;
        float4 qv = *(const float4*)(Qb + (size_t)(q0 + r) * CC + c);
        Qs[r][c + 0] = qv.x * scale;
        Qs[r][c + 1] = qv.y * scale;
        Qs[r][c + 2] = qv.z * scale;
        Qs[r][c + 3] = qv.w * scale;
    }

    float m[4], l[4], acc0[4], acc1[4];
#pragma unroll
    for (int i = 0; i < 4; i++) {
        m[i] = -1e30f; l[i] = 0.0f; acc0[i] = 0.0f; acc1[i] = 0.0f;
    }

    int kend = q0 + QROWS;  // exclusive bound on needed keys
    for (int kb = 0; kb < kend; kb += KT) {
        // load K & V tiles
        const float* Kb = Kb0 + (size_t)kb * CC;
        const float* Vb = Vb0 + (size_t)kb * CC;
        for (int idx = tid; idx < KT * (HD / 4); idx += 256) {
            int r = idx >> 4;
            int c = (idx & 15) * 4;
            float4 kv = *(const float4*)(Kb + (size_t)r * CC + c);
            Ks[r][c + 0] = kv.x; Ks[r][c + 1] = kv.y;
            Ks[r][c + 2] = kv.z; Ks[r][c + 3] = kv.w;
            float4 vv = *(const float4*)(Vb + (size_t)r * CC + c);
            Vs[r][c + 0] = vv.x; Vs[r][c + 1] = vv.y;
            Vs[r][c + 2] = vv.z; Vs[r][c + 3] = vv.w;
        }
        __syncthreads();

        // --- scores: s[i][0] = q_i . k_{lane}, s[i][1] = q_i . k_{lane+32}
        float s[4][2];
#pragma unroll
        for (int i = 0; i < 4; i++) { s[i][0] = 0.0f; s[i][1] = 0.0f; }
#pragma unroll
        for (int d = 0; d < HD; d++) {
            float k0v = Ks[lane][d];
            float k1v = Ks[lane + 32][d];
#pragma unroll
            for (int i = 0; i < 4; i++) {
                float qv = Qs[warp * 4 + i][d];
                s[i][0] += qv * k0v;
                s[i][1] += qv * k1v;
            }
        }

        // --- per-row online softmax state update
        float p0[4], p1[4];
#pragma unroll
        for (int i = 0; i < 4; i++) {
            int t = q0 + warp * 4 + i;
            float s0 = (kb + lane      <= t) ? s[i][0] : -1e30f;
            float s1 = (kb + lane + 32 <= t) ? s[i][1] : -1e30f;
            float mt = fmaxf(s0, s1);
#pragma unroll
            for (int o = 16; o > 0; o >>= 1)
                mt = fmaxf(mt, __shfl_xor_sync(0xffffffffu, mt, o));
            float mnew = fmaxf(m[i], mt);
            float e0 = __expf(s0 - mnew);
            float e1 = __expf(s1 - mnew);
            float ls = e0 + e1;
#pragma unroll
            for (int o = 16; o > 0; o >>= 1)
                ls += __shfl_xor_sync(0xffffffffu, ls, o);
            float alpha = __expf(m[i] - mnew);
            m[i] = mnew;
            l[i] = l[i] * alpha + ls;
            acc0[i] *= alpha;
            acc1[i] *= alpha;
            p0[i] = e0;
            p1[i] = e1;
        }

        // --- O += P @ V (k outer so Vs loads are shared across 4 rows)
#pragma unroll
        for (int kk = 0; kk < 32; kk++) {
            float v0 = Vs[kk][lane];
            float v1 = Vs[kk][lane + 32];
#pragma unroll
            for (int i = 0; i < 4; i++) {
                float p = __shfl_sync(0xffffffffu, p0[i], kk);
                acc0[i] += p * v0;
                acc1[i] += p * v1;
            }
        }
#pragma unroll
        for (int kk = 0; kk < 32; kk++) {
            float v0 = Vs[kk + 32][lane];
            float v1 = Vs[kk + 32][lane + 32];
#pragma unroll
            for (int i = 0; i < 4; i++) {
                float p = __shfl_sync(0xffffffffu, p1[i], kk);
                acc0[i] += p * v0;
                acc1[i] += p * v1;
            }
        }
        __syncthreads();
    }

    // epilogue
#pragma unroll
    for (int i = 0; i < 4; i++) {
        int t = q0 + warp * 4 + i;
        float inv = 1.0f / l[i];
        float* Op = O + (size_t)(b * TT + t) * CC + h * HD;
        Op[lane]      = acc0[i] * inv;
        Op[lane + 32] = acc1[i] * inv;
    }
}

// ---------------------------------------------------------------------------
// Launch
// ---------------------------------------------------------------------------
extern "C" void kernel_launch(void* const* d_in, const int* in_sizes, int n_in,
                              void* d_out, int out_size)
{
    const float* x  = (const float*)d_in[0];
    // d_in[1] = mask (causal tril; implemented analytically)
    const float* wq = (const float*)d_in[2];
    const float* bq = (const float*)d_in[3];
    const float* wk = (const float*)d_in[4];
    const float* bk = (const float*)d_in[5];
    const float* wv = (const float*)d_in[6];
    const float* bv = (const float*)d_in[7];
    const float* wo = (const float*)d_in[8];
    const float* bo = (const float*)d_in[9];
    float* out = (float*)d_out;

    float *q, *k, *v, *att;
    cudaGetSymbolAddress((void**)&q,   g_q);
    cudaGetSymbolAddress((void**)&k,   g_k);
    cudaGetSymbolAddress((void**)&v,   g_v);
    cudaGetSymbolAddress((void**)&att, g_att);

    dim3 ggrid(CC / 64, MROWS / 64);   // (12, 128)
    gemm_bias_kernel<<<ggrid, 256>>>(x, wq, bq, q, MROWS, CC, CC);
    gemm_bias_kernel<<<ggrid, 256>>>(x, wk, bk, k, MROWS, CC, CC);
    gemm_bias_kernel<<<ggrid, 256>>>(x, wv, bv, v, MROWS, CC, CC);

    dim3 agrid(TT / 32, HH, BB);       // (32, 12, 8)
    attn_kernel<<<agrid, 256>>>(q, k, v, att);

    gemm_bias_kernel<<<ggrid, 256>>>(att, wo, bo, out, MROWS, CC, CC);
}

// round 3
// speedup vs baseline: 1.6716x; 1.6716x over previous
#include <cuda_runtime.h>
#include <cuda_bf16.h>
#include <cstdint>
#include <math.h>

// Problem constants
#define BB 8
#define TT 1024
#define CC 768
#define HH 12
#define HD 64
#define MROWS (BB * TT)   // 8192

// ---------------------------------------------------------------------------
// Scratch (allocation-free: __device__ globals)
// ---------------------------------------------------------------------------
__device__ float g_q[MROWS * CC];
__device__ float g_k[MROWS * CC];
__device__ float g_v[MROWS * CC];
__device__ float g_att[MROWS * CC];
__device__ __nv_bfloat16 g_xh[MROWS * CC];
__device__ __nv_bfloat16 g_xl[MROWS * CC];
__device__ __nv_bfloat16 g_ah[MROWS * CC];
__device__ __nv_bfloat16 g_al[MROWS * CC];
__device__ __nv_bfloat16 g_wqh[CC * CC];
__device__ __nv_bfloat16 g_wql[CC * CC];
__device__ __nv_bfloat16 g_wkh[CC * CC];
__device__ __nv_bfloat16 g_wkl[CC * CC];
__device__ __nv_bfloat16 g_wvh[CC * CC];
__device__ __nv_bfloat16 g_wvl[CC * CC];
__device__ __nv_bfloat16 g_woh[CC * CC];
__device__ __nv_bfloat16 g_wol[CC * CC];

// ---------------------------------------------------------------------------
// PTX helpers (base sm_103 target: mma.sync / ldmatrix / cp.async only)
// ---------------------------------------------------------------------------
__device__ __forceinline__ uint32_t smem_u32(const void* p) {
    uint32_t a;
    asm("{ .reg .u64 t; cvta.to.shared.u64 t, %1; cvt.u32.u64 %0, t; }"
        : "=r"(a) : "l"(p));
    return a;
}
__device__ __forceinline__ void ldsm4(uint32_t* r, uint32_t a) {
    asm volatile("ldmatrix.sync.aligned.m8n8.x4.shared.b16 {%0,%1,%2,%3}, [%4];"
        : "=r"(r[0]), "=r"(r[1]), "=r"(r[2]), "=r"(r[3]) : "r"(a));
}
__device__ __forceinline__ void mma_bf16(float* d, const uint32_t* a,
                                         const uint32_t* b) {
    asm volatile(
        "mma.sync.aligned.m16n8k16.row.col.f32.bf16.bf16.f32 "
        "{%0,%1,%2,%3}, {%4,%5,%6,%7}, {%8,%9}, {%0,%1,%2,%3};"
        : "+f"(d[0]), "+f"(d[1]), "+f"(d[2]), "+f"(d[3])
        : "r"(a[0]), "r"(a[1]), "r"(a[2]), "r"(a[3]), "r"(b[0]), "r"(b[1]));
}
__device__ __forceinline__ void cp16(uint32_t dst, const void* src) {
    asm volatile("cp.async.cg.shared.global [%0], [%1], 16;"
                 :: "r"(dst), "l"(src));
}
#define CP_COMMIT() asm volatile("cp.async.commit_group;" ::: "memory")
#define CP_WAIT(n)  asm volatile("cp.async.wait_group %0;" :: "n"(n) : "memory")

// ---------------------------------------------------------------------------
// Split/conversion kernels
// ---------------------------------------------------------------------------
__global__ __launch_bounds__(256) void split_kernel(
    const float* __restrict__ x, __nv_bfloat16* __restrict__ h,
    __nv_bfloat16* __restrict__ l, int n4)
{
    int i = blockIdx.x * 256 + threadIdx.x;
    if (i >= n4) return;
    float4 v = ((const float4*)x)[i];
    __nv_bfloat16 h0 = __float2bfloat16(v.x);
    __nv_bfloat16 h1 = __float2bfloat16(v.y);
    __nv_bfloat16 h2 = __float2bfloat16(v.z);
    __nv_bfloat16 h3 = __float2bfloat16(v.w);
    __nv_bfloat16 l0 = __float2bfloat16(v.x - __bfloat162float(h0));
    __nv_bfloat16 l1 = __float2bfloat16(v.y - __bfloat162float(h1));
    __nv_bfloat16 l2 = __float2bfloat16(v.z - __bfloat162float(h2));
    __nv_bfloat16 l3 = __float2bfloat16(v.w - __bfloat162float(h3));
    __nv_bfloat162* hp = (__nv_bfloat162*)h;
    __nv_bfloat162* lp = (__nv_bfloat162*)l;
    hp[2 * i]     = __nv_bfloat162(h0, h1);
    hp[2 * i + 1] = __nv_bfloat162(h2, h3);
    lp[2 * i]     = __nv_bfloat162(l0, l1);
    lp[2 * i + 1] = __nv_bfloat162(l2, l3);
}

// W [K,N] fp32 -> Th/Tl [N,K] bf16 (transposed, split)
__global__ __launch_bounds__(256) void transpose_split_kernel(
    const float* __restrict__ W, __nv_bfloat16* __restrict__ Th,
    __nv_bfloat16* __restrict__ Tl)
{
    __shared__ float t[32][33];
    int n0 = blockIdx.x * 32, k0 = blockIdx.y * 32;
    int tx = threadIdx.x & 31, ty = threadIdx.x >> 5;  // 32 x 8
#pragma unroll
    for (int i = 0; i < 32; i += 8)
        t[ty + i][tx] = W[(size_t)(k0 + ty + i) * CC + n0 + tx];
    __syncthreads();
#pragma unroll
    for (int i = 0; i < 32; i += 8) {
        float v = t[tx][ty + i];
        __nv_bfloat16 hv = __float2bfloat16(v);
        Th[(size_t)(n0 + ty + i) * CC + k0 + tx] = hv;
        Tl[(size_t)(n0 + ty + i) * CC + k0 + tx] =
            __float2bfloat16(v - __bfloat162float(hv));
    }
}

// ---------------------------------------------------------------------------
// mma.sync bf16-split GEMM: C[8192,768] = (Ah+Al) @ (Wh+Wl)^T + bias
// W stored transposed [N,K]. CTA tile 128x64, BK=32, double-buffered cp.async.
// 8 warps (4x2), warp tile 32x32. D = Ah*Wh + Ah*Wl + Al*Wh, fp32 accum.
// ---------------------------------------------------------------------------
#define Bb_M 128
#define Bb_N 64
#define Bb_K 32
#define NKC (CC / Bb_K)          // 24
#define PAD 8
#define LDT (Bb_K + PAD)         // 40 bf16 per row (80B, 16B-aligned rows)
#define A_TILE_B (Bb_M * LDT * 2)   // 10240 bytes
#define B_TILE_B (Bb_N * LDT * 2)   // 5120 bytes
#define STAGE_B (2 * A_TILE_B + 2 * B_TILE_B)  // 30720
#define BIAS_OFF (2 * STAGE_B)
#define MM_SMEM (BIAS_OFF + Bb_N * 4)          // 61696

__device__ __forceinline__ void mm_load_stage(
    uint32_t base, const __nv_bfloat16* Ah, const __nv_bfloat16* Al,
    const __nv_bfloat16* Wh, const __nv_bfloat16* Wl,
    int bm, int bn, int k0, int tid)
{
#pragma unroll
    for (int t = 0; t < 2; t++) {
        int idx = t * 256 + tid;          // 0..511
        int row = idx >> 2, ck = idx & 3;
        uint32_t so = (uint32_t)(row * LDT + ck * 8) * 2;
        const size_t go = (size_t)(bm + row) * CC + k0 + ck * 8;
        cp16(base + so, Ah + go);
        cp16(base + A_TILE_B + so, Al + go);
    }
    {
        int row = tid >> 2, ck = tid & 3;  // 64 rows x 4 chunks
        uint32_t so = (uint32_t)(row * LDT + ck * 8) * 2;
        const size_t go = (size_t)(bn + row) * CC + k0 + ck * 8;
        cp16(base + 2 * A_TILE_B + so, Wh + go);
        cp16(base + 2 * A_TILE_B + B_TILE_B + so, Wl + go);
    }
}

__global__ __launch_bounds__(256) void mm_split_kernel(
    const __nv_bfloat16* __restrict__ Ah, const __nv_bfloat16* __restrict__ Al,
    const __nv_bfloat16* __restrict__ Wh, const __nv_bfloat16* __restrict__ Wl,
    const float* __restrict__ bias, float* __restrict__ C)
{
    extern __shared__ __align__(128) char smem[];
    uint32_t sb = smem_u32(smem);
    int tid = threadIdx.x;
    int lane = tid & 31, wid = tid >> 5;
    int wm = wid >> 1, wn = wid & 1;       // 4 x 2 warp grid
    int bn = blockIdx.x * Bb_N;
    int bm = blockIdx.y * Bb_M;

    if (tid < Bb_N) ((float*)(smem + BIAS_OFF))[tid] = bias[bn + tid];

    float acc[2][4][4];
#pragma unroll
    for (int mt = 0; mt < 2; mt++)
#pragma unroll
        for (int nt = 0; nt < 4; nt++)
#pragma unroll
            for (int j = 0; j < 4; j++) acc[mt][nt][j] = 0.0f;

    mm_load_stage(sb, Ah, Al, Wh, Wl, bm, bn, 0, tid);
    CP_COMMIT();

    // ldmatrix lane addressing (element offsets within a tile)
    const uint32_t a_row = lane & 15;
    const uint32_t a_col = (lane >> 4) * 8;
    const uint32_t b_row = ((lane >> 4) * 8) + (lane & 7);
    const uint32_t b_col = ((lane >> 3) & 1) * 8;

    for (int c = 0; c < NKC; c++) {
        if (c + 1 < NKC) {
            mm_load_stage(sb + ((c + 1) & 1) * STAGE_B, Ah, Al, Wh, Wl,
                          bm, bn, (c + 1) * Bb_K, tid);
            CP_COMMIT();
            CP_WAIT(1);
        } else {
            CP_WAIT(0);
        }
        __syncthreads();

        uint32_t base = sb + (c & 1) * STAGE_B;
#pragma unroll
        for (int ks = 0; ks < 2; ks++) {
            uint32_t ah[2][4], al[2][4];
#pragma unroll
            for (int mt = 0; mt < 2; mt++) {
                uint32_t off = ((wm * 32 + mt * 16 + a_row) * LDT +
                                ks * 16 + a_col) * 2;
                ldsm4(ah[mt], base + off);
                ldsm4(al[mt], base + A_TILE_B + off);
            }
            uint32_t bh[4][2], bl[4][2];
#pragma unroll
            for (int nt16 = 0; nt16 < 2; nt16++) {
                uint32_t off = ((wn * 32 + nt16 * 16 + b_row) * LDT +
                                ks * 16 + b_col) * 2;
                uint32_t r4[4], s4[4];
                ldsm4(r4, base + 2 * A_TILE_B + off);
                ldsm4(s4, base + 2 * A_TILE_B + B_TILE_B + off);
                bh[nt16 * 2][0] = r4[0]; bh[nt16 * 2][1] = r4[1];
                bh[nt16 * 2 + 1][0] = r4[2]; bh[nt16 * 2 + 1][1] = r4[3];
                bl[nt16 * 2][0] = s4[0]; bl[nt16 * 2][1] = s4[1];
                bl[nt16 * 2 + 1][0] = s4[2]; bl[nt16 * 2 + 1][1] = s4[3];
            }
#pragma unroll
            for (int mt = 0; mt < 2; mt++)
#pragma unroll
                for (int nt = 0; nt < 4; nt++) {
                    mma_bf16(acc[mt][nt], ah[mt], bh[nt]);
                    mma_bf16(acc[mt][nt], ah[mt], bl[nt]);
                    mma_bf16(acc[mt][nt], al[mt], bh[nt]);
                }
        }
        __syncthreads();
    }

    // epilogue: C = acc + bias
    const float* bs = (const float*)(smem + BIAS_OFF);
#pragma unroll
    for (int mt = 0; mt < 2; mt++) {
        int row0 = bm + wm * 32 + mt * 16 + (lane >> 2);
#pragma unroll
        for (int nt = 0; nt < 4; nt++) {
            int coll = wn * 32 + nt * 8 + (lane & 3) * 2;
            float bx = bs[coll], by = bs[coll + 1];
            float2 o0 = { acc[mt][nt][0] + bx, acc[mt][nt][1] + by };
            float2 o1 = { acc[mt][nt][2] + bx, acc[mt][nt][3] + by };
            *(float2*)(C + (size_t)row0 * CC + bn + coll) = o0;
            *(float2*)(C + (size_t)(row0 + 8) * CC + bn + coll) = o1;
        }
    }
}

// ---------------------------------------------------------------------------
// Causal flash attention (unchanged — known good, 613us)
// ---------------------------------------------------------------------------
__global__ __launch_bounds__(256) void attn_kernel(
    const float* __restrict__ Q, const float* __restrict__ K,
    const float* __restrict__ V, float* __restrict__ O)
{
    const int QROWS = 32, KT = 64;
    __shared__ float Qs[QROWS][HD + 1];
    __shared__ float Ks[KT][HD + 1];
    __shared__ float Vs[KT][HD + 1];

    int tid = threadIdx.x;
    int warp = tid >> 5, lane = tid & 31;
    int b = blockIdx.z, h = blockIdx.y;
    int q0 = blockIdx.x * QROWS;
    const float scale = 0.125f;

    const float* Qb = Q + (size_t)(b * TT) * CC + h * HD;
    const float* Kb0 = K + (size_t)(b * TT) * CC + h * HD;
    const float* Vb0 = V + (size_t)(b * TT) * CC + h * HD;

    for (int idx = tid; idx < QROWS * (HD / 4); idx += 256) {
        int r = idx >> 4;
        int c = (idx & 15) * 4;
        float4 qv = *(const float4*)(Qb + (size_t)(q0 + r) * CC + c);
        Qs[r][c + 0] = qv.x * scale;
        Qs[r][c + 1] = qv.y * scale;
        Qs[r][c + 2] = qv.z * scale;
        Qs[r][c + 3] = qv.w * scale;
    }

    float m[4], l[4], acc0[4], acc1[4];
#pragma unroll
    for (int i = 0; i < 4; i++) {
        m[i] = -1e30f; l[i] = 0.0f; acc0[i] = 0.0f; acc1[i] = 0.0f;
    }

    int kend = q0 + QROWS;
    for (int kb = 0; kb < kend; kb += KT) {
        const float* Kb = Kb0 + (size_t)kb * CC;
        const float* Vb = Vb0 + (size_t)kb * CC;
        for (int idx = tid; idx < KT * (HD / 4); idx += 256) {
            int r = idx >> 4;
            int c = (idx & 15) * 4;
            float4 kv = *(const float4*)(Kb + (size_t)r * CC + c);
            Ks[r][c + 0] = kv.x; Ks[r][c + 1] = kv.y;
            Ks[r][c + 2] = kv.z; Ks[r][c + 3] = kv.w;
            float4 vv = *(const float4*)(Vb + (size_t)r * CC + c);
            Vs[r][c + 0] = vv.x; Vs[r][c + 1] = vv.y;
            Vs[r][c + 2] = vv.z; Vs[r][c + 3] = vv.w;
        }
        __syncthreads();

        float s[4][2];
#pragma unroll
        for (int i = 0; i < 4; i++) { s[i][0] = 0.0f; s[i][1] = 0.0f; }
#pragma unroll
        for (int d = 0; d < HD; d++) {
            float k0v = Ks[lane][d];
            float k1v = Ks[lane + 32][d];
#pragma unroll
            for (int i = 0; i < 4; i++) {
                float qv = Qs[warp * 4 + i][d];
                s[i][0] += qv * k0v;
                s[i][1] += qv * k1v;
            }
        }

        float p0[4], p1[4];
#pragma unroll
        for (int i = 0; i < 4; i++) {
            int t = q0 + warp * 4 + i;
            float s0 = (kb + lane      <= t) ? s[i][0] : -1e30f;
            float s1 = (kb + lane + 32 <= t) ? s[i][1] : -1e30f;
            float mt = fmaxf(s0, s1);
#pragma unroll
            for (int o = 16; o > 0; o >>= 1)
                mt = fmaxf(mt, __shfl_xor_sync(0xffffffffu, mt, o));
            float mnew = fmaxf(m[i], mt);
            float e0 = __expf(s0 - mnew);
            float e1 = __expf(s1 - mnew);
            float ls = e0 + e1;
#pragma unroll
            for (int o = 16; o > 0; o >>= 1)
                ls += __shfl_xor_sync(0xffffffffu, ls, o);
            float alpha = __expf(m[i] - mnew);
            m[i] = mnew;
            l[i] = l[i] * alpha + ls;
            acc0[i] *= alpha;
            acc1[i] *= alpha;
            p0[i] = e0;
            p1[i] = e1;
        }

#pragma unroll
        for (int kk = 0; kk < 32; kk++) {
            float v0 = Vs[kk][lane];
            float v1 = Vs[kk][lane + 32];
#pragma unroll
            for (int i = 0; i < 4; i++) {
                float p = __shfl_sync(0xffffffffu, p0[i], kk);
                acc0[i] += p * v0;
                acc1[i] += p * v1;
            }
        }
#pragma unroll
        for (int kk = 0; kk < 32; kk++) {
            float v0 = Vs[kk + 32][lane];
            float v1 = Vs[kk + 32][lane + 32];
#pragma unroll
            for (int i = 0; i < 4; i++) {
                float p = __shfl_sync(0xffffffffu, p1[i], kk);
                acc0[i] += p * v0;
                acc1[i] += p * v1;
            }
        }
        __syncthreads();
    }

#pragma unroll
    for (int i = 0; i < 4; i++) {
        int t = q0 + warp * 4 + i;
        float inv = 1.0f / l[i];
        float* Op = O + (size_t)(b * TT + t) * CC + h * HD;
        Op[lane]      = acc0[i] * inv;
        Op[lane + 32] = acc1[i] * inv;
    }
}

// ---------------------------------------------------------------------------
// Launch
// ---------------------------------------------------------------------------
extern "C" void kernel_launch(void* const* d_in, const int* in_sizes, int n_in,
                              void* d_out, int out_size)
{
    const float* x  = (const float*)d_in[0];
    const float* wq = (const float*)d_in[2];
    const float* bq = (const float*)d_in[3];
    const float* wk = (const float*)d_in[4];
    const float* bk = (const float*)d_in[5];
    const float* wv = (const float*)d_in[6];
    const float* bv = (const float*)d_in[7];
    const float* wo = (const float*)d_in[8];
    const float* bo = (const float*)d_in[9];
    float* out = (float*)d_out;

    float *q, *k, *v, *att;
    __nv_bfloat16 *xh, *xl, *ah, *al;
    __nv_bfloat16 *wqh, *wql, *wkh, *wkl, *wvh, *wvl, *woh, *wol;
    cudaGetSymbolAddress((void**)&q,   g_q);
    cudaGetSymbolAddress((void**)&k,   g_k);
    cudaGetSymbolAddress((void**)&v,   g_v);
    cudaGetSymbolAddress((void**)&att, g_att);
    cudaGetSymbolAddress((void**)&xh,  g_xh);
    cudaGetSymbolAddress((void**)&xl,  g_xl);
    cudaGetSymbolAddress((void**)&ah,  g_ah);
    cudaGetSymbolAddress((void**)&al,  g_al);
    cudaGetSymbolAddress((void**)&wqh, g_wqh);
    cudaGetSymbolAddress((void**)&wql, g_wql);
    cudaGetSymbolAddress((void**)&wkh, g_wkh);
    cudaGetSymbolAddress((void**)&wkl, g_wkl);
    cudaGetSymbolAddress((void**)&wvh, g_wvh);
    cudaGetSymbolAddress((void**)&wvl, g_wvl);
    cudaGetSymbolAddress((void**)&woh, g_woh);
    cudaGetSymbolAddress((void**)&wol, g_wol);

    cudaFuncSetAttribute(mm_split_kernel,
                         cudaFuncAttributeMaxDynamicSharedMemorySize, MM_SMEM);

    // split x into bf16 hi/lo
    int n4 = MROWS * CC / 4;
    split_kernel<<<(n4 + 255) / 256, 256>>>(x, xh, xl, n4);

    // transpose + split weights: [K,N] fp32 -> [N,K] bf16 hi/lo
    dim3 tgrid(CC / 32, CC / 32);
    transpose_split_kernel<<<tgrid, 256>>>(wq, wqh, wql);
    transpose_split_kernel<<<tgrid, 256>>>(wk, wkh, wkl);
    transpose_split_kernel<<<tgrid, 256>>>(wv, wvh, wvl);
    transpose_split_kernel<<<tgrid, 256>>>(wo, woh, wol);

    // QKV projections (tensor core via mma.sync)
    dim3 ggrid(CC / Bb_N, MROWS / Bb_M);   // (12, 64)
    mm_split_kernel<<<ggrid, 256, MM_SMEM>>>(xh, xl, wqh, wql, bq, q);
    mm_split_kernel<<<ggrid, 256, MM_SMEM>>>(xh, xl, wkh, wkl, bk, k);
    mm_split_kernel<<<ggrid, 256, MM_SMEM>>>(xh, xl, wvh, wvl, bv, v);

    // attention
    dim3 agrid(TT / 32, HH, BB);
    attn_kernel<<<agrid, 256>>>(q, k, v, att);

    // output projection
    split_kernel<<<(n4 + 255) / 256, 256>>>(att, ah, al, n4);
    mm_split_kernel<<<ggrid, 256, MM_SMEM>>>(ah, al, woh, wol, bo, out);
}

// round 4
// speedup vs baseline: 2.9427x; 1.7604x over previous
#include <cuda_runtime.h>
#include <cuda_bf16.h>
#include <cstdint>
#include <math.h>

// Problem constants
#define BB 8
#define TT 1024
#define CC 768
#define HH 12
#define HD 64
#define MROWS (BB * TT)   // 8192

// ---------------------------------------------------------------------------
// Scratch (allocation-free: __device__ globals)
// ---------------------------------------------------------------------------
__device__ __nv_bfloat16 g_xh[MROWS * CC];
__device__ __nv_bfloat16 g_xl[MROWS * CC];
__device__ __nv_bfloat16 g_qh[MROWS * CC];
__device__ __nv_bfloat16 g_ql[MROWS * CC];
__device__ __nv_bfloat16 g_kh[MROWS * CC];
__device__ __nv_bfloat16 g_kl[MROWS * CC];
__device__ __nv_bfloat16 g_vh[MROWS * CC];
__device__ __nv_bfloat16 g_vl[MROWS * CC];
__device__ __nv_bfloat16 g_ah[MROWS * CC];
__device__ __nv_bfloat16 g_al[MROWS * CC];
__device__ __nv_bfloat16 g_wqh[CC * CC];
__device__ __nv_bfloat16 g_wql[CC * CC];
__device__ __nv_bfloat16 g_wkh[CC * CC];
__device__ __nv_bfloat16 g_wkl[CC * CC];
__device__ __nv_bfloat16 g_wvh[CC * CC];
__device__ __nv_bfloat16 g_wvl[CC * CC];
__device__ __nv_bfloat16 g_woh[CC * CC];
__device__ __nv_bfloat16 g_wol[CC * CC];

// ---------------------------------------------------------------------------
// PTX helpers (base sm_103 target: mma.sync / ldmatrix / cp.async only)
// ---------------------------------------------------------------------------
__device__ __forceinline__ uint32_t smem_u32(const void* p) {
    uint32_t a;
    asm("{ .reg .u64 t; cvta.to.shared.u64 t, %1; cvt.u32.u64 %0, t; }"
        : "=r"(a) : "l"(p));
    return a;
}
__device__ __forceinline__ void ldsm4(uint32_t* r, uint32_t a) {
    asm volatile("ldmatrix.sync.aligned.m8n8.x4.shared.b16 {%0,%1,%2,%3}, [%4];"
        : "=r"(r[0]), "=r"(r[1]), "=r"(r[2]), "=r"(r[3]) : "r"(a));
}
__device__ __forceinline__ void ldsm4t(uint32_t* r, uint32_t a) {
    asm volatile("ldmatrix.sync.aligned.m8n8.x4.trans.shared.b16 {%0,%1,%2,%3}, [%4];"
        : "=r"(r[0]), "=r"(r[1]), "=r"(r[2]), "=r"(r[3]) : "r"(a));
}
__device__ __forceinline__ void mma_bf16(float* d, const uint32_t* a,
                                         const uint32_t* b) {
    asm volatile(
        "mma.sync.aligned.m16n8k16.row.col.f32.bf16.bf16.f32 "
        "{%0,%1,%2,%3}, {%4,%5,%6,%7}, {%8,%9}, {%0,%1,%2,%3};"
        : "+f"(d[0]), "+f"(d[1]), "+f"(d[2]), "+f"(d[3])
        : "r"(a[0]), "r"(a[1]), "r"(a[2]), "r"(a[3]), "r"(b[0]), "r"(b[1]));
}
__device__ __forceinline__ void cp16(uint32_t dst, const void* src) {
    asm volatile("cp.async.cg.shared.global [%0], [%1], 16;"
                 :: "r"(dst), "l"(src));
}
#define CP_COMMIT() asm volatile("cp.async.commit_group;" ::: "memory")
#define CP_WAIT(n)  asm volatile("cp.async.wait_group %0;" :: "n"(n) : "memory")

__device__ __forceinline__ uint32_t pack2(__nv_bfloat16 lo, __nv_bfloat16 hi) {
    uint16_t a = *(uint16_t*)&lo, b = *(uint16_t*)&hi;
    return (uint32_t)a | ((uint32_t)b << 16);
}

// ---------------------------------------------------------------------------
// Split/conversion kernels
// ---------------------------------------------------------------------------
__global__ __launch_bounds__(256) void split_kernel(
    const float* __restrict__ x, __nv_bfloat16* __restrict__ h,
    __nv_bfloat16* __restrict__ l, int n4)
{
    int i = blockIdx.x * 256 + threadIdx.x;
    if (i >= n4) return;
    float4 v = ((const float4*)x)[i];
    __nv_bfloat16 h0 = __float2bfloat16(v.x);
    __nv_bfloat16 h1 = __float2bfloat16(v.y);
    __nv_bfloat16 h2 = __float2bfloat16(v.z);
    __nv_bfloat16 h3 = __float2bfloat16(v.w);
    __nv_bfloat16 l0 = __float2bfloat16(v.x - __bfloat162float(h0));
    __nv_bfloat16 l1 = __float2bfloat16(v.y - __bfloat162float(h1));
    __nv_bfloat16 l2 = __float2bfloat16(v.z - __bfloat162float(h2));
    __nv_bfloat16 l3 = __float2bfloat16(v.w - __bfloat162float(h3));
    __nv_bfloat162* hp = (__nv_bfloat162*)h;
    __nv_bfloat162* lp = (__nv_bfloat162*)l;
    hp[2 * i]     = __nv_bfloat162(h0, h1);
    hp[2 * i + 1] = __nv_bfloat162(h2, h3);
    lp[2 * i]     = __nv_bfloat162(l0, l1);
    lp[2 * i + 1] = __nv_bfloat162(l2, l3);
}

// W [K,N] fp32 -> Th/Tl [N,K] bf16 (transposed, split)
__global__ __launch_bounds__(256) void transpose_split_kernel(
    const float* __restrict__ W, __nv_bfloat16* __restrict__ Th,
    __nv_bfloat16* __restrict__ Tl)
{
    __shared__ float t[32][33];
    int n0 = blockIdx.x * 32, k0 = blockIdx.y * 32;
    int tx = threadIdx.x & 31, ty = threadIdx.x >> 5;  // 32 x 8
#pragma unroll
    for (int i = 0; i < 32; i += 8)
        t[ty + i][tx] = W[(size_t)(k0 + ty + i) * CC + n0 + tx];
    __syncthreads();
#pragma unroll
    for (int i = 0; i < 32; i += 8) {
        float v = t[tx][ty + i];
        __nv_bfloat16 hv = __float2bfloat16(v);
        Th[(size_t)(n0 + ty + i) * CC + k0 + tx] = hv;
        Tl[(size_t)(n0 + ty + i) * CC + k0 + tx] =
            __float2bfloat16(v - __bfloat162float(hv));
    }
}

// ---------------------------------------------------------------------------
// mma.sync bf16-split GEMM: out = ((Ah+Al) @ (Wh+Wl)^T + bias) * scale
// W stored transposed [N,K]. CTA tile 128x64, BK=32, double-buffered cp.async.
// Epilogue: either fp32 (Cf) or fused bf16 hi/lo split (Ch, Cl).
// ---------------------------------------------------------------------------
#define Bb_M 128
#define Bb_N 64
#define Bb_K 32
#define NKC (CC / Bb_K)          // 24
#define PAD 8
#define LDT (Bb_K + PAD)         // 40 bf16 per row
#define A_TILE_B (Bb_M * LDT * 2)
#define B_TILE_B (Bb_N * LDT * 2)
#define STAGE_B (2 * A_TILE_B + 2 * B_TILE_B)
#define BIAS_OFF (2 * STAGE_B)
#define MM_SMEM (BIAS_OFF + Bb_N * 4)

__device__ __forceinline__ void mm_load_stage(
    uint32_t base, const __nv_bfloat16* Ah, const __nv_bfloat16* Al,
    const __nv_bfloat16* Wh, const __nv_bfloat16* Wl,
    int bm, int bn, int k0, int tid)
{
#pragma unroll
    for (int t = 0; t < 2; t++) {
        int idx = t * 256 + tid;
        int row = idx >> 2, ck = idx & 3;
        uint32_t so = (uint32_t)(row * LDT + ck * 8) * 2;
        const size_t go = (size_t)(bm + row) * CC + k0 + ck * 8;
        cp16(base + so, Ah + go);
        cp16(base + A_TILE_B + so, Al + go);
    }
    {
        int row = tid >> 2, ck = tid & 3;
        uint32_t so = (uint32_t)(row * LDT + ck * 8) * 2;
        const size_t go = (size_t)(bn + row) * CC + k0 + ck * 8;
        cp16(base + 2 * A_TILE_B + so, Wh + go);
        cp16(base + 2 * A_TILE_B + B_TILE_B + so, Wl + go);
    }
}

__global__ __launch_bounds__(256) void mm_split_kernel(
    const __nv_bfloat16* __restrict__ Ah, const __nv_bfloat16* __restrict__ Al,
    const __nv_bfloat16* __restrict__ Wh, const __nv_bfloat16* __restrict__ Wl,
    const float* __restrict__ bias, float scale,
    float* __restrict__ Cf, __nv_bfloat16* __restrict__ Ch,
    __nv_bfloat16* __restrict__ Cl)
{
    extern __shared__ __align__(128) char smem[];
    uint32_t sb = smem_u32(smem);
    int tid = threadIdx.x;
    int lane = tid & 31, wid = tid >> 5;
    int wm = wid >> 1, wn = wid & 1;
    int bn = blockIdx.x * Bb_N;
    int bm = blockIdx.y * Bb_M;

    if (tid < Bb_N) ((float*)(smem + BIAS_OFF))[tid] = bias[bn + tid];

    float acc[2][4][4];
#pragma unroll
    for (int mt = 0; mt < 2; mt++)
#pragma unroll
        for (int nt = 0; nt < 4; nt++)
#pragma unroll
            for (int j = 0; j < 4; j++) acc[mt][nt][j] = 0.0f;

    mm_load_stage(sb, Ah, Al, Wh, Wl, bm, bn, 0, tid);
    CP_COMMIT();

    const uint32_t a_row = lane & 15;
    const uint32_t a_col = (lane >> 4) * 8;
    const uint32_t b_row = ((lane >> 4) * 8) + (lane & 7);
    const uint32_t b_col = ((lane >> 3) & 1) * 8;

    for (int c = 0; c < NKC; c++) {
        if (c + 1 < NKC) {
            mm_load_stage(sb + ((c + 1) & 1) * STAGE_B, Ah, Al, Wh, Wl,
                          bm, bn, (c + 1) * Bb_K, tid);
            CP_COMMIT();
            CP_WAIT(1);
        } else {
            CP_WAIT(0);
        }
        __syncthreads();

        uint32_t base = sb + (c & 1) * STAGE_B;
#pragma unroll
        for (int ks = 0; ks < 2; ks++) {
            uint32_t ah[2][4], al[2][4];
#pragma unroll
            for (int mt = 0; mt < 2; mt++) {
                uint32_t off = ((wm * 32 + mt * 16 + a_row) * LDT +
                                ks * 16 + a_col) * 2;
                ldsm4(ah[mt], base + off);
                ldsm4(al[mt], base + A_TILE_B + off);
            }
            uint32_t bh[4][2], bl[4][2];
#pragma unroll
            for (int nt16 = 0; nt16 < 2; nt16++) {
                uint32_t off = ((wn * 32 + nt16 * 16 + b_row) * LDT +
                                ks * 16 + b_col) * 2;
                uint32_t r4[4], s4[4];
                ldsm4(r4, base + 2 * A_TILE_B + off);
                ldsm4(s4, base + 2 * A_TILE_B + B_TILE_B + off);
                bh[nt16 * 2][0] = r4[0]; bh[nt16 * 2][1] = r4[1];
                bh[nt16 * 2 + 1][0] = r4[2]; bh[nt16 * 2 + 1][1] = r4[3];
                bl[nt16 * 2][0] = s4[0]; bl[nt16 * 2][1] = s4[1];
                bl[nt16 * 2 + 1][0] = s4[2]; bl[nt16 * 2 + 1][1] = s4[3];
            }
#pragma unroll
            for (int mt = 0; mt < 2; mt++)
#pragma unroll
                for (int nt = 0; nt < 4; nt++) {
                    mma_bf16(acc[mt][nt], ah[mt], bh[nt]);
                    mma_bf16(acc[mt][nt], ah[mt], bl[nt]);
                    mma_bf16(acc[mt][nt], al[mt], bh[nt]);
                }
        }
        __syncthreads();
    }

    // epilogue
    const float* bs = (const float*)(smem + BIAS_OFF);
#pragma unroll
    for (int mt = 0; mt < 2; mt++) {
        int row0 = bm + wm * 32 + mt * 16 + (lane >> 2);
#pragma unroll
        for (int nt = 0; nt < 4; nt++) {
            int coll = wn * 32 + nt * 8 + (lane & 3) * 2;
            float bx = bs[coll], by = bs[coll + 1];
            float o0 = (acc[mt][nt][0] + bx) * scale;
            float o1 = (acc[mt][nt][1] + by) * scale;
            float o2 = (acc[mt][nt][2] + bx) * scale;
            float o3 = (acc[mt][nt][3] + by) * scale;
            size_t i0 = (size_t)row0 * CC + bn + coll;
            size_t i1 = (size_t)(row0 + 8) * CC + bn + coll;
            if (Cf) {
                *(float2*)(Cf + i0) = make_float2(o0, o1);
                *(float2*)(Cf + i1) = make_float2(o2, o3);
            } else {
                __nv_bfloat16 h0 = __float2bfloat16(o0);
                __nv_bfloat16 h1 = __float2bfloat16(o1);
                __nv_bfloat16 h2 = __float2bfloat16(o2);
                __nv_bfloat16 h3 = __float2bfloat16(o3);
                *(uint32_t*)(Ch + i0) = pack2(h0, h1);
                *(uint32_t*)(Ch + i1) = pack2(h2, h3);
                *(uint32_t*)(Cl + i0) = pack2(
                    __float2bfloat16(o0 - __bfloat162float(h0)),
                    __float2bfloat16(o1 - __bfloat162float(h1)));
                *(uint32_t*)(Cl + i1) = pack2(
                    __float2bfloat16(o2 - __bfloat162float(h2)),
                    __float2bfloat16(o3 - __bfloat162float(h3)));
            }
        }
    }
}

// ---------------------------------------------------------------------------
// Tensor-core causal flash attention (bf16 split, mma.sync).
// CTA: 64 Q-rows, 4 warps (16 rows each). K/V blocks of 64, double-buffered.
// Q pre-scaled by 1/8 at split time.
// ---------------------------------------------------------------------------
#define AQ 64
#define AK 64
#define LDA 72
#define ATILE_B (64 * LDA * 2)       // 9216
#define AKV_OFF (2 * ATILE_B)        // Q hi/lo first
#define ASTAGE_B (4 * ATILE_B)
#define ATT_SMEM (AKV_OFF + 2 * ASTAGE_B)   // 92160

__global__ __launch_bounds__(128) void attn_mma_kernel(
    const __nv_bfloat16* __restrict__ qh, const __nv_bfloat16* __restrict__ ql,
    const __nv_bfloat16* __restrict__ kh, const __nv_bfloat16* __restrict__ kl,
    const __nv_bfloat16* __restrict__ vh, const __nv_bfloat16* __restrict__ vl,
    __nv_bfloat16* __restrict__ oh, __nv_bfloat16* __restrict__ ol)
{
    extern __shared__ __align__(128) char smem[];
    uint32_t sb = smem_u32(smem);
    int tid = threadIdx.x, lane = tid & 31, w = tid >> 5;
    int b = blockIdx.z, h = blockIdx.y;
    int q0 = (int)(gridDim.x - 1 - blockIdx.x) * AQ;   // long CTAs first
    const size_t gbase = (size_t)b * TT * CC + h * HD;

    // Q tile load (hi/lo), group 0
#pragma unroll
    for (int i = 0; i < 4; i++) {
        int idx = i * 128 + tid;
        int r = idx >> 3, ck = idx & 7;
        uint32_t so = (uint32_t)(r * LDA + ck * 8) * 2;
        size_t go = gbase + (size_t)(q0 + r) * CC + ck * 8;
        cp16(sb + so, qh + go);
        cp16(sb + ATILE_B + so, ql + go);
    }
    // KV stage 0, same group
    {
        uint32_t base = sb + AKV_OFF;
#pragma unroll
        for (int i = 0; i < 4; i++) {
            int idx = i * 128 + tid;
            int r = idx >> 3, ck = idx & 7;
            uint32_t so = (uint32_t)(r * LDA + ck * 8) * 2;
            size_t go = gbase + (size_t)r * CC + ck * 8;
            cp16(base + so, kh + go);
            cp16(base + ATILE_B + so, kl + go);
            cp16(base + 2 * ATILE_B + so, vh + go);
            cp16(base + 3 * ATILE_B + so, vl + go);
        }
    }
    CP_COMMIT();

    float oacc[8][4];
#pragma unroll
    for (int nt = 0; nt < 8; nt++)
#pragma unroll
        for (int j = 0; j < 4; j++) oacc[nt][j] = 0.0f;
    float m0 = -1e30f, m1 = -1e30f, l0 = 0.0f, l1 = 0.0f;

    uint32_t qfh[4][4], qfl[4][4];

    const int rl0 = w * 16 + (lane >> 2);  // local row 0 in 64-tile
    const int nkb = q0 / AK + 1;

    for (int c = 0; c < nkb; c++) {
        if (c + 1 < nkb) {
            uint32_t base = sb + AKV_OFF + ((c + 1) & 1) * ASTAGE_B;
            int kb1 = (c + 1) * AK;
#pragma unroll
            for (int i = 0; i < 4; i++) {
                int idx = i * 128 + tid;
                int r = idx >> 3, ck = idx & 7;
                uint32_t so = (uint32_t)(r * LDA + ck * 8) * 2;
                size_t go = gbase + (size_t)(kb1 + r) * CC + ck * 8;
                cp16(base + so, kh + go);
                cp16(base + ATILE_B + so, kl + go);
                cp16(base + 2 * ATILE_B + so, vh + go);
                cp16(base + 3 * ATILE_B + so, vl + go);
            }
            CP_COMMIT();
            CP_WAIT(1);
        } else {
            CP_WAIT(0);
        }
        __syncthreads();

        if (c == 0) {
            // load Q fragments once (smem now valid)
#pragma unroll
            for (int kc = 0; kc < 4; kc++) {
                uint32_t off = ((w * 16 + (lane & 15)) * LDA +
                                kc * 16 + (lane >> 4) * 8) * 2;
                ldsm4(qfh[kc], sb + off);
                ldsm4(qfl[kc], sb + ATILE_B + off);
            }
        }

        uint32_t kbase = sb + AKV_OFF + (c & 1) * ASTAGE_B;

        // ---- S = Q K^T (split) ----
        float sacc[8][4];
#pragma unroll
        for (int nt = 0; nt < 8; nt++)
#pragma unroll
            for (int j = 0; j < 4; j++) sacc[nt][j] = 0.0f;

#pragma unroll
        for (int kc = 0; kc < 4; kc++) {
#pragma unroll
            for (int nt16 = 0; nt16 < 4; nt16++) {
                uint32_t off = ((nt16 * 16 + (lane >> 4) * 8 + (lane & 7)) * LDA +
                                kc * 16 + ((lane >> 3) & 1) * 8) * 2;
                uint32_t rh[4], rl[4];
                ldsm4(rh, kbase + off);
                ldsm4(rl, kbase + ATILE_B + off);
                uint32_t bh0[2] = { rh[0], rh[1] }, bh1[2] = { rh[2], rh[3] };
                uint32_t bl0[2] = { rl[0], rl[1] }, bl1[2] = { rl[2], rl[3] };
                mma_bf16(sacc[2 * nt16],     qfh[kc], bh0);
                mma_bf16(sacc[2 * nt16],     qfh[kc], bl0);
                mma_bf16(sacc[2 * nt16],     qfl[kc], bh0);
                mma_bf16(sacc[2 * nt16 + 1], qfh[kc], bh1);
                mma_bf16(sacc[2 * nt16 + 1], qfh[kc], bl1);
                mma_bf16(sacc[2 * nt16 + 1], qfl[kc], bh1);
            }
        }

        // ---- causal mask on diagonal block ----
        int kb = c * AK;
        if (kb == q0) {
#pragma unroll
            for (int nt = 0; nt < 8; nt++) {
                int cl = nt * 8 + (lane & 3) * 2;
                if (cl     > rl0)     sacc[nt][0] = -1e30f;
                if (cl + 1 > rl0)     sacc[nt][1] = -1e30f;
                if (cl     > rl0 + 8) sacc[nt][2] = -1e30f;
                if (cl + 1 > rl0 + 8) sacc[nt][3] = -1e30f;
            }
        }

        // ---- online softmax ----
        float mx0 = -1e30f, mx1 = -1e30f;
#pragma unroll
        for (int nt = 0; nt < 8; nt++) {
            mx0 = fmaxf(mx0, fmaxf(sacc[nt][0], sacc[nt][1]));
            mx1 = fmaxf(mx1, fmaxf(sacc[nt][2], sacc[nt][3]));
        }
        mx0 = fmaxf(mx0, __shfl_xor_sync(0xffffffffu, mx0, 1));
        mx0 = fmaxf(mx0, __shfl_xor_sync(0xffffffffu, mx0, 2));
        mx1 = fmaxf(mx1, __shfl_xor_sync(0xffffffffu, mx1, 1));
        mx1 = fmaxf(mx1, __shfl_xor_sync(0xffffffffu, mx1, 2));
        float mn0 = fmaxf(m0, mx0), mn1 = fmaxf(m1, mx1);
        float al0 = __expf(m0 - mn0), al1 = __expf(m1 - mn1);
        m0 = mn0; m1 = mn1;

        float ls0 = 0.0f, ls1 = 0.0f;
#pragma unroll
        for (int nt = 0; nt < 8; nt++) {
            sacc[nt][0] = __expf(sacc[nt][0] - mn0);
            sacc[nt][1] = __expf(sacc[nt][1] - mn0);
            sacc[nt][2] = __expf(sacc[nt][2] - mn1);
            sacc[nt][3] = __expf(sacc[nt][3] - mn1);
            ls0 += sacc[nt][0] + sacc[nt][1];
            ls1 += sacc[nt][2] + sacc[nt][3];
        }
        l0 = l0 * al0 + ls0;
        l1 = l1 * al1 + ls1;
#pragma unroll
        for (int nt = 0; nt < 8; nt++) {
            oacc[nt][0] *= al0; oacc[nt][1] *= al0;
            oacc[nt][2] *= al1; oacc[nt][3] *= al1;
        }

        // ---- pack P into A fragments (hi + residual lo) ----
        uint32_t pfh[4][4], pfl[4][4];
#pragma unroll
        for (int kc = 0; kc < 4; kc++) {
#pragma unroll
            for (int half = 0; half < 2; half++) {   // tile 2kc+half
                int j = 2 * kc + half;
                float p0 = sacc[j][0], p1 = sacc[j][1];
                float p2 = sacc[j][2], p3 = sacc[j][3];
                __nv_bfloat16 h0 = __float2bfloat16(p0);
                __nv_bfloat16 h1 = __float2bfloat16(p1);
                __nv_bfloat16 h2 = __float2bfloat16(p2);
                __nv_bfloat16 h3 = __float2bfloat16(p3);
                pfh[kc][2 * half]     = pack2(h0, h1);
                pfh[kc][2 * half + 1] = pack2(h2, h3);
                pfl[kc][2 * half]     = pack2(
                    __float2bfloat16(p0 - __bfloat162float(h0)),
                    __float2bfloat16(p1 - __bfloat162float(h1)));
                pfl[kc][2 * half + 1] = pack2(
                    __float2bfloat16(p2 - __bfloat162float(h2)),
                    __float2bfloat16(p3 - __bfloat162float(h3)));
            }
        }
        // fragment order fix: a = {row_r k0-7, row_r+8 k0-7, row_r k8-15, row_r+8 k8-15}
        // pfh[kc] currently = {r,k0; r+8,k0; r,k8; r+8,k8} -> matches a0..a3. OK.

        // ---- O += P V (split) ----
        uint32_t vbase = kbase + 2 * ATILE_B;
#pragma unroll
        for (int kc = 0; kc < 4; kc++) {
#pragma unroll
            for (int nt16 = 0; nt16 < 4; nt16++) {
                uint32_t off = ((kc * 16 + ((lane >> 3) & 1) * 8 + (lane & 7)) * LDA +
                                nt16 * 16 + (lane >> 4) * 8) * 2;
                uint32_t rh[4], rl[4];
                ldsm4t(rh, vbase + off);
                ldsm4t(rl, vbase + ATILE_B + off);
                uint32_t bh0[2] = { rh[0], rh[1] }, bh1[2] = { rh[2], rh[3] };
                uint32_t bl0[2] = { rl[0], rl[1] }, bl1[2] = { rl[2], rl[3] };
                mma_bf16(oacc[2 * nt16],     pfh[kc], bh0);
                mma_bf16(oacc[2 * nt16],     pfl[kc], bh0);
                mma_bf16(oacc[2 * nt16],     pfh[kc], bl0);
                mma_bf16(oacc[2 * nt16 + 1], pfh[kc], bh1);
                mma_bf16(oacc[2 * nt16 + 1], pfl[kc], bh1);
                mma_bf16(oacc[2 * nt16 + 1], pfh[kc], bl1);
            }
        }
        __syncthreads();
    }

    // ---- epilogue: divide by l, split to bf16 hi/lo ----
    l0 += __shfl_xor_sync(0xffffffffu, l0, 1);
    l0 += __shfl_xor_sync(0xffffffffu, l0, 2);
    l1 += __shfl_xor_sync(0xffffffffu, l1, 1);
    l1 += __shfl_xor_sync(0xffffffffu, l1, 2);
    float li0 = 1.0f / l0, li1 = 1.0f / l1;

    size_t row0 = gbase + (size_t)(q0 + rl0) * CC;
    size_t row1 = row0 + 8 * CC;
#pragma unroll
    for (int nt = 0; nt < 8; nt++) {
        int cl = nt * 8 + (lane & 3) * 2;
        float o0 = oacc[nt][0] * li0, o1 = oacc[nt][1] * li0;
        float o2 = oacc[nt][2] * li1, o3 = oacc[nt][3] * li1;
        __nv_bfloat16 h0 = __float2bfloat16(o0);
        __nv_bfloat16 h1 = __float2bfloat16(o1);
        __nv_bfloat16 h2 = __float2bfloat16(o2);
        __nv_bfloat16 h3 = __float2bfloat16(o3);
        *(uint32_t*)(oh + row0 + cl) = pack2(h0, h1);
        *(uint32_t*)(oh + row1 + cl) = pack2(h2, h3);
        *(uint32_t*)(ol + row0 + cl) = pack2(
            __float2bfloat16(o0 - __bfloat162float(h0)),
            __float2bfloat16(o1 - __bfloat162float(h1)));
        *(uint32_t*)(ol + row1 + cl) = pack2(
            __float2bfloat16(o2 - __bfloat162float(h2)),
            __float2bfloat16(o3 - __bfloat162float(h3)));
    }
}

// ---------------------------------------------------------------------------
// Launch
// ---------------------------------------------------------------------------
extern "C" void kernel_launch(void* const* d_in, const int* in_sizes, int n_in,
                              void* d_out, int out_size)
{
    const float* x  = (const float*)d_in[0];
    const float* wq = (const float*)d_in[2];
    const float* bq = (const float*)d_in[3];
    const float* wk = (const float*)d_in[4];
    const float* bk = (const float*)d_in[5];
    const float* wv = (const float*)d_in[6];
    const float* bv = (const float*)d_in[7];
    const float* wo = (const float*)d_in[8];
    const float* bo = (const float*)d_in[9];
    float* out = (float*)d_out;

    __nv_bfloat16 *xh, *xl, *qh, *ql, *kh, *kl, *vh, *vl, *ah, *al;
    __nv_bfloat16 *wqh, *wql, *wkh, *wkl, *wvh, *wvl, *woh, *wol;
    cudaGetSymbolAddress((void**)&xh,  g_xh);
    cudaGetSymbolAddress((void**)&xl,  g_xl);
    cudaGetSymbolAddress((void**)&qh,  g_qh);
    cudaGetSymbolAddress((void**)&ql,  g_ql);
    cudaGetSymbolAddress((void**)&kh,  g_kh);
    cudaGetSymbolAddress((void**)&kl,  g_kl);
    cudaGetSymbolAddress((void**)&vh,  g_vh);
    cudaGetSymbolAddress((void**)&vl,  g_vl);
    cudaGetSymbolAddress((void**)&ah,  g_ah);
    cudaGetSymbolAddress((void**)&al,  g_al);
    cudaGetSymbolAddress((void**)&wqh, g_wqh);
    cudaGetSymbolAddress((void**)&wql, g_wql);
    cudaGetSymbolAddress((void**)&wkh, g_wkh);
    cudaGetSymbolAddress((void**)&wkl, g_wkl);
    cudaGetSymbolAddress((void**)&wvh, g_wvh);
    cudaGetSymbolAddress((void**)&wvl, g_wvl);
    cudaGetSymbolAddress((void**)&woh, g_woh);
    cudaGetSymbolAddress((void**)&wol, g_wol);

    cudaFuncSetAttribute(mm_split_kernel,
                         cudaFuncAttributeMaxDynamicSharedMemorySize, MM_SMEM);
    cudaFuncSetAttribute(attn_mma_kernel,
                         cudaFuncAttributeMaxDynamicSharedMemorySize, ATT_SMEM);

    // split x into bf16 hi/lo
    int n4 = MROWS * CC / 4;
    split_kernel<<<(n4 + 255) / 256, 256>>>(x, xh, xl, n4);

    // transpose + split weights
    dim3 tgrid(CC / 32, CC / 32);
    transpose_split_kernel<<<tgrid, 256>>>(wq, wqh, wql);
    transpose_split_kernel<<<tgrid, 256>>>(wk, wkh, wkl);
    transpose_split_kernel<<<tgrid, 256>>>(wv, wvh, wvl);
    transpose_split_kernel<<<tgrid, 256>>>(wo, woh, wol);

    // QKV projections; q scaled by 1/8; epilogue writes bf16 hi/lo directly
    dim3 ggrid(CC / Bb_N, MROWS / Bb_M);   // (12, 64)
    mm_split_kernel<<<ggrid, 256, MM_SMEM>>>(xh, xl, wqh, wql, bq, 0.125f,
                                             nullptr, qh, ql);
    mm_split_kernel<<<ggrid, 256, MM_SMEM>>>(xh, xl, wkh, wkl, bk, 1.0f,
                                             nullptr, kh, kl);
    mm_split_kernel<<<ggrid, 256, MM_SMEM>>>(xh, xl, wvh, wvl, bv, 1.0f,
                                             nullptr, vh, vl);

    // tensor-core flash attention
    dim3 agrid(TT / AQ, HH, BB);           // (16, 12, 8)
    attn_mma_kernel<<<agrid, 128, ATT_SMEM>>>(qh, ql, kh, kl, vh, vl, ah, al);

    // output projection (fp32 out)
    mm_split_kernel<<<ggrid, 256, MM_SMEM>>>(ah, al, woh, wol, bo, 1.0f,
                                             out, nullptr, nullptr);
}

// round 5
// speedup vs baseline: 3.0576x; 1.0391x over previous
#include <cuda_runtime.h>
#include <cuda_bf16.h>
#include <cstdint>
#include <math.h>

// Problem constants
#define BB 8
#define TT 1024
#define CC 768
#define HH 12
#define HD 64
#define MROWS (BB * TT)   // 8192

// ---------------------------------------------------------------------------
// Scratch (allocation-free: __device__ globals)
// ---------------------------------------------------------------------------
__device__ __nv_bfloat16 g_xh[MROWS * CC];
__device__ __nv_bfloat16 g_xl[MROWS * CC];
__device__ __nv_bfloat16 g_qh[MROWS * CC];
__device__ __nv_bfloat16 g_ql[MROWS * CC];
__device__ __nv_bfloat16 g_kh[MROWS * CC];
__device__ __nv_bfloat16 g_kl[MROWS * CC];
__device__ __nv_bfloat16 g_vh[MROWS * CC];
__device__ __nv_bfloat16 g_vl[MROWS * CC];
__device__ __nv_bfloat16 g_ah[MROWS * CC];
__device__ __nv_bfloat16 g_al[MROWS * CC];
__device__ __nv_bfloat16 g_wqh[CC * CC];
__device__ __nv_bfloat16 g_wql[CC * CC];
__device__ __nv_bfloat16 g_wkh[CC * CC];
__device__ __nv_bfloat16 g_wkl[CC * CC];
__device__ __nv_bfloat16 g_wvh[CC * CC];
__device__ __nv_bfloat16 g_wvl[CC * CC];
__device__ __nv_bfloat16 g_woh[CC * CC];
__device__ __nv_bfloat16 g_wol[CC * CC];

// ---------------------------------------------------------------------------
// PTX helpers (base sm_103 target: mma.sync / ldmatrix / cp.async only)
// ---------------------------------------------------------------------------
__device__ __forceinline__ uint32_t smem_u32(const void* p) {
    uint32_t a;
    asm("{ .reg .u64 t; cvta.to.shared.u64 t, %1; cvt.u32.u64 %0, t; }"
        : "=r"(a) : "l"(p));
    return a;
}
__device__ __forceinline__ void ldsm4(uint32_t* r, uint32_t a) {
    asm volatile("ldmatrix.sync.aligned.m8n8.x4.shared.b16 {%0,%1,%2,%3}, [%4];"
        : "=r"(r[0]), "=r"(r[1]), "=r"(r[2]), "=r"(r[3]) : "r"(a));
}
__device__ __forceinline__ void ldsm4t(uint32_t* r, uint32_t a) {
    asm volatile("ldmatrix.sync.aligned.m8n8.x4.trans.shared.b16 {%0,%1,%2,%3}, [%4];"
        : "=r"(r[0]), "=r"(r[1]), "=r"(r[2]), "=r"(r[3]) : "r"(a));
}
__device__ __forceinline__ void mma_bf16(float* d, const uint32_t* a,
                                         const uint32_t* b) {
    asm volatile(
        "mma.sync.aligned.m16n8k16.row.col.f32.bf16.bf16.f32 "
        "{%0,%1,%2,%3}, {%4,%5,%6,%7}, {%8,%9}, {%0,%1,%2,%3};"
        : "+f"(d[0]), "+f"(d[1]), "+f"(d[2]), "+f"(d[3])
        : "r"(a[0]), "r"(a[1]), "r"(a[2]), "r"(a[3]), "r"(b[0]), "r"(b[1]));
}
__device__ __forceinline__ void cp16(uint32_t dst, const void* src) {
    asm volatile("cp.async.cg.shared.global [%0], [%1], 16;"
                 :: "r"(dst), "l"(src));
}
#define CP_COMMIT() asm volatile("cp.async.commit_group;" ::: "memory")
#define CP_WAIT(n)  asm volatile("cp.async.wait_group %0;" :: "n"(n) : "memory")

__device__ __forceinline__ uint32_t pack2(__nv_bfloat16 lo, __nv_bfloat16 hi) {
    uint16_t a = *(uint16_t*)&lo, b = *(uint16_t*)&hi;
    return (uint32_t)a | ((uint32_t)b << 16);
}

// ---------------------------------------------------------------------------
// Split/conversion kernels
// ---------------------------------------------------------------------------
__global__ __launch_bounds__(256) void split_kernel(
    const float* __restrict__ x, __nv_bfloat16* __restrict__ h,
    __nv_bfloat16* __restrict__ l, int n4)
{
    int i = blockIdx.x * 256 + threadIdx.x;
    if (i >= n4) return;
    float4 v = ((const float4*)x)[i];
    __nv_bfloat16 h0 = __float2bfloat16(v.x);
    __nv_bfloat16 h1 = __float2bfloat16(v.y);
    __nv_bfloat16 h2 = __float2bfloat16(v.z);
    __nv_bfloat16 h3 = __float2bfloat16(v.w);
    __nv_bfloat16 l0 = __float2bfloat16(v.x - __bfloat162float(h0));
    __nv_bfloat16 l1 = __float2bfloat16(v.y - __bfloat162float(h1));
    __nv_bfloat16 l2 = __float2bfloat16(v.z - __bfloat162float(h2));
    __nv_bfloat16 l3 = __float2bfloat16(v.w - __bfloat162float(h3));
    __nv_bfloat162* hp = (__nv_bfloat162*)h;
    __nv_bfloat162* lp = (__nv_bfloat162*)l;
    hp[2 * i]     = __nv_bfloat162(h0, h1);
    hp[2 * i + 1] = __nv_bfloat162(h2, h3);
    lp[2 * i]     = __nv_bfloat162(l0, l1);
    lp[2 * i + 1] = __nv_bfloat162(l2, l3);
}

// W [K,N] fp32 -> Th/Tl [N,K] bf16 (transposed, split)
__global__ __launch_bounds__(256) void transpose_split_kernel(
    const float* __restrict__ W, __nv_bfloat16* __restrict__ Th,
    __nv_bfloat16* __restrict__ Tl)
{
    __shared__ float t[32][33];
    int n0 = blockIdx.x * 32, k0 = blockIdx.y * 32;
    int tx = threadIdx.x & 31, ty = threadIdx.x >> 5;  // 32 x 8
#pragma unroll
    for (int i = 0; i < 32; i += 8)
        t[ty + i][tx] = W[(size_t)(k0 + ty + i) * CC + n0 + tx];
    __syncthreads();
#pragma unroll
    for (int i = 0; i < 32; i += 8) {
        float v = t[tx][ty + i];
        __nv_bfloat16 hv = __float2bfloat16(v);
        Th[(size_t)(n0 + ty + i) * CC + k0 + tx] = hv;
        Tl[(size_t)(n0 + ty + i) * CC + k0 + tx] =
            __float2bfloat16(v - __bfloat162float(hv));
    }
}

// ---------------------------------------------------------------------------
// mma.sync bf16-split GEMM: out = ((Ah+Al) @ (Wh+Wl)^T + bias) * scale
// W stored transposed [N,K]. CTA tile 128x128, BK=32, double-buffered cp.async.
// 8 warps (4x2), warp tile 32x64. D = Ah*Wh + Ah*Wl + Al*Wh, fp32 accum.
// ---------------------------------------------------------------------------
#define Bb_M 128
#define Bb_N 128
#define Bb_K 32
#define NKC (CC / Bb_K)          // 24
#define PAD 8
#define LDT (Bb_K + PAD)         // 40 bf16 per row
#define A_TILE_B (Bb_M * LDT * 2)   // 10240
#define B_TILE_B (Bb_N * LDT * 2)   // 10240
#define STAGE_B (2 * A_TILE_B + 2 * B_TILE_B)  // 40960
#define BIAS_OFF (2 * STAGE_B)
#define MM_SMEM (BIAS_OFF + Bb_N * 4)          // 82432

__device__ __forceinline__ void mm_load_stage(
    uint32_t base, const __nv_bfloat16* Ah, const __nv_bfloat16* Al,
    const __nv_bfloat16* Wh, const __nv_bfloat16* Wl,
    int bm, int bn, int k0, int tid)
{
#pragma unroll
    for (int t = 0; t < 2; t++) {
        int idx = t * 256 + tid;          // 0..511
        int row = idx >> 2, ck = idx & 3;
        uint32_t so = (uint32_t)(row * LDT + ck * 8) * 2;
        const size_t goA = (size_t)(bm + row) * CC + k0 + ck * 8;
        const size_t goB = (size_t)(bn + row) * CC + k0 + ck * 8;
        cp16(base + so, Ah + goA);
        cp16(base + A_TILE_B + so, Al + goA);
        cp16(base + 2 * A_TILE_B + so, Wh + goB);
        cp16(base + 2 * A_TILE_B + B_TILE_B + so, Wl + goB);
    }
}

__global__ __launch_bounds__(256) void mm_split_kernel(
    const __nv_bfloat16* __restrict__ Ah, const __nv_bfloat16* __restrict__ Al,
    const __nv_bfloat16* __restrict__ Wh, const __nv_bfloat16* __restrict__ Wl,
    const float* __restrict__ bias, float scale,
    float* __restrict__ Cf, __nv_bfloat16* __restrict__ Ch,
    __nv_bfloat16* __restrict__ Cl)
{
    extern __shared__ __align__(128) char smem[];
    uint32_t sb = smem_u32(smem);
    int tid = threadIdx.x;
    int lane = tid & 31, wid = tid >> 5;
    int wm = wid >> 1, wn = wid & 1;       // 4 x 2 warp grid: 32 rows x 64 cols
    int bn = blockIdx.x * Bb_N;
    int bm = blockIdx.y * Bb_M;

    if (tid < Bb_N) ((float*)(smem + BIAS_OFF))[tid] = bias[bn + tid];

    float acc[2][8][4];
#pragma unroll
    for (int mt = 0; mt < 2; mt++)
#pragma unroll
        for (int nt = 0; nt < 8; nt++)
#pragma unroll
            for (int j = 0; j < 4; j++) acc[mt][nt][j] = 0.0f;

    mm_load_stage(sb, Ah, Al, Wh, Wl, bm, bn, 0, tid);
    CP_COMMIT();

    const uint32_t a_row = lane & 15;
    const uint32_t a_col = (lane >> 4) * 8;
    const uint32_t b_row = ((lane >> 4) * 8) + (lane & 7);
    const uint32_t b_col = ((lane >> 3) & 1) * 8;

    for (int c = 0; c < NKC; c++) {
        if (c + 1 < NKC) {
            mm_load_stage(sb + ((c + 1) & 1) * STAGE_B, Ah, Al, Wh, Wl,
                          bm, bn, (c + 1) * Bb_K, tid);
            CP_COMMIT();
            CP_WAIT(1);
        } else {
            CP_WAIT(0);
        }
        __syncthreads();

        uint32_t base = sb + (c & 1) * STAGE_B;
#pragma unroll
        for (int ks = 0; ks < 2; ks++) {
            uint32_t ah[2][4], al[2][4];
#pragma unroll
            for (int mt = 0; mt < 2; mt++) {
                uint32_t off = ((wm * 32 + mt * 16 + a_row) * LDT +
                                ks * 16 + a_col) * 2;
                ldsm4(ah[mt], base + off);
                ldsm4(al[mt], base + A_TILE_B + off);
            }
            uint32_t bh[8][2], bl[8][2];
#pragma unroll
            for (int nt16 = 0; nt16 < 4; nt16++) {
                uint32_t off = ((wn * 64 + nt16 * 16 + b_row) * LDT +
                                ks * 16 + b_col) * 2;
                uint32_t r4[4], s4[4];
                ldsm4(r4, base + 2 * A_TILE_B + off);
                ldsm4(s4, base + 2 * A_TILE_B + B_TILE_B + off);
                bh[nt16 * 2][0] = r4[0]; bh[nt16 * 2][1] = r4[1];
                bh[nt16 * 2 + 1][0] = r4[2]; bh[nt16 * 2 + 1][1] = r4[3];
                bl[nt16 * 2][0] = s4[0]; bl[nt16 * 2][1] = s4[1];
                bl[nt16 * 2 + 1][0] = s4[2]; bl[nt16 * 2 + 1][1] = s4[3];
            }
#pragma unroll
            for (int mt = 0; mt < 2; mt++)
#pragma unroll
                for (int nt = 0; nt < 8; nt++) {
                    mma_bf16(acc[mt][nt], ah[mt], bh[nt]);
                    mma_bf16(acc[mt][nt], ah[mt], bl[nt]);
                    mma_bf16(acc[mt][nt], al[mt], bh[nt]);
                }
        }
        __syncthreads();
    }

    // epilogue
    const float* bs = (const float*)(smem + BIAS_OFF);
#pragma unroll
    for (int mt = 0; mt < 2; mt++) {
        int row0 = bm + wm * 32 + mt * 16 + (lane >> 2);
#pragma unroll
        for (int nt = 0; nt < 8; nt++) {
            int coll = wn * 64 + nt * 8 + (lane & 3) * 2;
            float bx = bs[coll], by = bs[coll + 1];
            float o0 = (acc[mt][nt][0] + bx) * scale;
            float o1 = (acc[mt][nt][1] + by) * scale;
            float o2 = (acc[mt][nt][2] + bx) * scale;
            float o3 = (acc[mt][nt][3] + by) * scale;
            size_t i0 = (size_t)row0 * CC + bn + coll;
            size_t i1 = (size_t)(row0 + 8) * CC + bn + coll;
            if (Cf) {
                *(float2*)(Cf + i0) = make_float2(o0, o1);
                *(float2*)(Cf + i1) = make_float2(o2, o3);
            } else {
                __nv_bfloat16 h0 = __float2bfloat16(o0);
                __nv_bfloat16 h1 = __float2bfloat16(o1);
                __nv_bfloat16 h2 = __float2bfloat16(o2);
                __nv_bfloat16 h3 = __float2bfloat16(o3);
                *(uint32_t*)(Ch + i0) = pack2(h0, h1);
                *(uint32_t*)(Ch + i1) = pack2(h2, h3);
                *(uint32_t*)(Cl + i0) = pack2(
                    __float2bfloat16(o0 - __bfloat162float(h0)),
                    __float2bfloat16(o1 - __bfloat162float(h1)));
                *(uint32_t*)(Cl + i1) = pack2(
                    __float2bfloat16(o2 - __bfloat162float(h2)),
                    __float2bfloat16(o3 - __bfloat162float(h3)));
            }
        }
    }
}

// ---------------------------------------------------------------------------
// Tensor-core causal flash attention (bf16 split, mma.sync). Unchanged.
// CTA: 64 Q-rows, 4 warps (16 rows each). K/V blocks of 64, double-buffered.
// Q pre-scaled by 1/8 at split time.
// ---------------------------------------------------------------------------
#define AQ 64
#define AK 64
#define LDA 72
#define ATILE_B (64 * LDA * 2)       // 9216
#define AKV_OFF (2 * ATILE_B)
#define ASTAGE_B (4 * ATILE_B)
#define ATT_SMEM (AKV_OFF + 2 * ASTAGE_B)   // 92160

__global__ __launch_bounds__(128) void attn_mma_kernel(
    const __nv_bfloat16* __restrict__ qh, const __nv_bfloat16* __restrict__ ql,
    const __nv_bfloat16* __restrict__ kh, const __nv_bfloat16* __restrict__ kl,
    const __nv_bfloat16* __restrict__ vh, const __nv_bfloat16* __restrict__ vl,
    __nv_bfloat16* __restrict__ oh, __nv_bfloat16* __restrict__ ol)
{
    extern __shared__ __align__(128) char smem[];
    uint32_t sb = smem_u32(smem);
    int tid = threadIdx.x, lane = tid & 31, w = tid >> 5;
    int b = blockIdx.z, h = blockIdx.y;
    int q0 = (int)(gridDim.x - 1 - blockIdx.x) * AQ;
    const size_t gbase = (size_t)b * TT * CC + h * HD;

#pragma unroll
    for (int i = 0; i < 4; i++) {
        int idx = i * 128 + tid;
        int r = idx >> 3, ck = idx & 7;
        uint32_t so = (uint32_t)(r * LDA + ck * 8) * 2;
        size_t go = gbase + (size_t)(q0 + r) * CC + ck * 8;
        cp16(sb + so, qh + go);
        cp16(sb + ATILE_B + so, ql + go);
    }
    {
        uint32_t base = sb + AKV_OFF;
#pragma unroll
        for (int i = 0; i < 4; i++) {
            int idx = i * 128 + tid;
            int r = idx >> 3, ck = idx & 7;
            uint32_t so = (uint32_t)(r * LDA + ck * 8) * 2;
            size_t go = gbase + (size_t)r * CC + ck * 8;
            cp16(base + so, kh + go);
            cp16(base + ATILE_B + so, kl + go);
            cp16(base + 2 * ATILE_B + so, vh + go);
            cp16(base + 3 * ATILE_B + so, vl + go);
        }
    }
    CP_COMMIT();

    float oacc[8][4];
#pragma unroll
    for (int nt = 0; nt < 8; nt++)
#pragma unroll
        for (int j = 0; j < 4; j++) oacc[nt][j] = 0.0f;
    float m0 = -1e30f, m1 = -1e30f, l0 = 0.0f, l1 = 0.0f;

    uint32_t qfh[4][4], qfl[4][4];

    const int rl0 = w * 16 + (lane >> 2);
    const int nkb = q0 / AK + 1;

    for (int c = 0; c < nkb; c++) {
        if (c + 1 < nkb) {
            uint32_t base = sb + AKV_OFF + ((c + 1) & 1) * ASTAGE_B;
            int kb1 = (c + 1) * AK;
#pragma unroll
            for (int i = 0; i < 4; i++) {
                int idx = i * 128 + tid;
                int r = idx >> 3, ck = idx & 7;
                uint32_t so = (uint32_t)(r * LDA + ck * 8) * 2;
                size_t go = gbase + (size_t)(kb1 + r) * CC + ck * 8;
                cp16(base + so, kh + go);
                cp16(base + ATILE_B + so, kl + go);
                cp16(base + 2 * ATILE_B + so, vh + go);
                cp16(base + 3 * ATILE_B + so, vl + go);
            }
            CP_COMMIT();
            CP_WAIT(1);
        } else {
            CP_WAIT(0);
        }
        __syncthreads();

        if (c == 0) {
#pragma unroll
            for (int kc = 0; kc < 4; kc++) {
                uint32_t off = ((w * 16 + (lane & 15)) * LDA +
                                kc * 16 + (lane >> 4) * 8) * 2;
                ldsm4(qfh[kc], sb + off);
                ldsm4(qfl[kc], sb + ATILE_B + off);
            }
        }

        uint32_t kbase = sb + AKV_OFF + (c & 1) * ASTAGE_B;

        float sacc[8][4];
#pragma unroll
        for (int nt = 0; nt < 8; nt++)
#pragma unroll
            for (int j = 0; j < 4; j++) sacc[nt][j] = 0.0f;

#pragma unroll
        for (int kc = 0; kc < 4; kc++) {
#pragma unroll
            for (int nt16 = 0; nt16 < 4; nt16++) {
                uint32_t off = ((nt16 * 16 + (lane >> 4) * 8 + (lane & 7)) * LDA +
                                kc * 16 + ((lane >> 3) & 1) * 8) * 2;
                uint32_t rh[4], rl[4];
                ldsm4(rh, kbase + off);
                ldsm4(rl, kbase + ATILE_B + off);
                uint32_t bh0[2] = { rh[0], rh[1] }, bh1[2] = { rh[2], rh[3] };
                uint32_t bl0[2] = { rl[0], rl[1] }, bl1[2] = { rl[2], rl[3] };
                mma_bf16(sacc[2 * nt16],     qfh[kc], bh0);
                mma_bf16(sacc[2 * nt16],     qfh[kc], bl0);
                mma_bf16(sacc[2 * nt16],     qfl[kc], bh0);
                mma_bf16(sacc[2 * nt16 + 1], qfh[kc], bh1);
                mma_bf16(sacc[2 * nt16 + 1], qfh[kc], bl1);
                mma_bf16(sacc[2 * nt16 + 1], qfl[kc], bh1);
            }
        }

        int kb = c * AK;
        if (kb == q0) {
#pragma unroll
            for (int nt = 0; nt < 8; nt++) {
                int cl = nt * 8 + (lane & 3) * 2;
                if (cl     > rl0)     sacc[nt][0] = -1e30f;
                if (cl + 1 > rl0)     sacc[nt][1] = -1e30f;
                if (cl     > rl0 + 8) sacc[nt][2] = -1e30f;
                if (cl + 1 > rl0 + 8) sacc[nt][3] = -1e30f;
            }
        }

        float mx0 = -1e30f, mx1 = -1e30f;
#pragma unroll
        for (int nt = 0; nt < 8; nt++) {
            mx0 = fmaxf(mx0, fmaxf(sacc[nt][0], sacc[nt][1]));
            mx1 = fmaxf(mx1, fmaxf(sacc[nt][2], sacc[nt][3]));
        }
        mx0 = fmaxf(mx0, __shfl_xor_sync(0xffffffffu, mx0, 1));
        mx0 = fmaxf(mx0, __shfl_xor_sync(0xffffffffu, mx0, 2));
        mx1 = fmaxf(mx1, __shfl_xor_sync(0xffffffffu, mx1, 1));
        mx1 = fmaxf(mx1, __shfl_xor_sync(0xffffffffu, mx1, 2));
        float mn0 = fmaxf(m0, mx0), mn1 = fmaxf(m1, mx1);
        float al0 = __expf(m0 - mn0), al1 = __expf(m1 - mn1);
        m0 = mn0; m1 = mn1;

        float ls0 = 0.0f, ls1 = 0.0f;
#pragma unroll
        for (int nt = 0; nt < 8; nt++) {
            sacc[nt][0] = __expf(sacc[nt][0] - mn0);
            sacc[nt][1] = __expf(sacc[nt][1] - mn0);
            sacc[nt][2] = __expf(sacc[nt][2] - mn1);
            sacc[nt][3] = __expf(sacc[nt][3] - mn1);
            ls0 += sacc[nt][0] + sacc[nt][1];
            ls1 += sacc[nt][2] + sacc[nt][3];
        }
        l0 = l0 * al0 + ls0;
        l1 = l1 * al1 + ls1;
#pragma unroll
        for (int nt = 0; nt < 8; nt++) {
            oacc[nt][0] *= al0; oacc[nt][1] *= al0;
            oacc[nt][2] *= al1; oacc[nt][3] *= al1;
        }

        uint32_t pfh[4][4], pfl[4][4];
#pragma unroll
        for (int kc = 0; kc < 4; kc++) {
#pragma unroll
            for (int half = 0; half < 2; half++) {
                int j = 2 * kc + half;
                float p0 = sacc[j][0], p1 = sacc[j][1];
                float p2 = sacc[j][2], p3 = sacc[j][3];
                __nv_bfloat16 h0 = __float2bfloat16(p0);
                __nv_bfloat16 h1 = __float2bfloat16(p1);
                __nv_bfloat16 h2 = __float2bfloat16(p2);
                __nv_bfloat16 h3 = __float2bfloat16(p3);
                pfh[kc][2 * half]     = pack2(h0, h1);
                pfh[kc][2 * half + 1] = pack2(h2, h3);
                pfl[kc][2 * half]     = pack2(
                    __float2bfloat16(p0 - __bfloat162float(h0)),
                    __float2bfloat16(p1 - __bfloat162float(h1)));
                pfl[kc][2 * half + 1] = pack2(
                    __float2bfloat16(p2 - __bfloat162float(h2)),
                    __float2bfloat16(p3 - __bfloat162float(h3)));
            }
        }

        uint32_t vbase = kbase + 2 * ATILE_B;
#pragma unroll
        for (int kc = 0; kc < 4; kc++) {
#pragma unroll
            for (int nt16 = 0; nt16 < 4; nt16++) {
                uint32_t off = ((kc * 16 + ((lane >> 3) & 1) * 8 + (lane & 7)) * LDA +
                                nt16 * 16 + (lane >> 4) * 8) * 2;
                uint32_t rh[4], rl[4];
                ldsm4t(rh, vbase + off);
                ldsm4t(rl, vbase + ATILE_B + off);
                uint32_t bh0[2] = { rh[0], rh[1] }, bh1[2] = { rh[2], rh[3] };
                uint32_t bl0[2] = { rl[0], rl[1] }, bl1[2] = { rl[2], rl[3] };
                mma_bf16(oacc[2 * nt16],     pfh[kc], bh0);
                mma_bf16(oacc[2 * nt16],     pfl[kc], bh0);
                mma_bf16(oacc[2 * nt16],     pfh[kc], bl0);
                mma_bf16(oacc[2 * nt16 + 1], pfh[kc], bh1);
                mma_bf16(oacc[2 * nt16 + 1], pfl[kc], bh1);
                mma_bf16(oacc[2 * nt16 + 1], pfh[kc], bl1);
            }
        }
        __syncthreads();
    }

    l0 += __shfl_xor_sync(0xffffffffu, l0, 1);
    l0 += __shfl_xor_sync(0xffffffffu, l0, 2);
    l1 += __shfl_xor_sync(0xffffffffu, l1, 1);
    l1 += __shfl_xor_sync(0xffffffffu, l1, 2);
    float li0 = 1.0f / l0, li1 = 1.0f / l1;

    size_t row0 = gbase + (size_t)(q0 + rl0) * CC;
    size_t row1 = row0 + 8 * CC;
#pragma unroll
    for (int nt = 0; nt < 8; nt++) {
        int cl = nt * 8 + (lane & 3) * 2;
        float o0 = oacc[nt][0] * li0, o1 = oacc[nt][1] * li0;
        float o2 = oacc[nt][2] * li1, o3 = oacc[nt][3] * li1;
        __nv_bfloat16 h0 = __float2bfloat16(o0);
        __nv_bfloat16 h1 = __float2bfloat16(o1);
        __nv_bfloat16 h2 = __float2bfloat16(o2);
        __nv_bfloat16 h3 = __float2bfloat16(o3);
        *(uint32_t*)(oh + row0 + cl) = pack2(h0, h1);
        *(uint32_t*)(oh + row1 + cl) = pack2(h2, h3);
        *(uint32_t*)(ol + row0 + cl) = pack2(
            __float2bfloat16(o0 - __bfloat162float(h0)),
            __float2bfloat16(o1 - __bfloat162float(h1)));
        *(uint32_t*)(ol + row1 + cl) = pack2(
            __float2bfloat16(o2 - __bfloat162float(h2)),
            __float2bfloat16(o3 - __bfloat162float(h3)));
    }
}

// ---------------------------------------------------------------------------
// Launch
// ---------------------------------------------------------------------------
extern "C" void kernel_launch(void* const* d_in, const int* in_sizes, int n_in,
                              void* d_out, int out_size)
{
    const float* x  = (const float*)d_in[0];
    const float* wq = (const float*)d_in[2];
    const float* bq = (const float*)d_in[3];
    const float* wk = (const float*)d_in[4];
    const float* bk = (const float*)d_in[5];
    const float* wv = (const float*)d_in[6];
    const float* bv = (const float*)d_in[7];
    const float* wo = (const float*)d_in[8];
    const float* bo = (const float*)d_in[9];
    float* out = (float*)d_out;

    __nv_bfloat16 *xh, *xl, *qh, *ql, *kh, *kl, *vh, *vl, *ah, *al;
    __nv_bfloat16 *wqh, *wql, *wkh, *wkl, *wvh, *wvl, *woh, *wol;
    cudaGetSymbolAddress((void**)&xh,  g_xh);
    cudaGetSymbolAddress((void**)&xl,  g_xl);
    cudaGetSymbolAddress((void**)&qh,  g_qh);
    cudaGetSymbolAddress((void**)&ql,  g_ql);
    cudaGetSymbolAddress((void**)&kh,  g_kh);
    cudaGetSymbolAddress((void**)&kl,  g_kl);
    cudaGetSymbolAddress((void**)&vh,  g_vh);
    cudaGetSymbolAddress((void**)&vl,  g_vl);
    cudaGetSymbolAddress((void**)&ah,  g_ah);
    cudaGetSymbolAddress((void**)&al,  g_al);
    cudaGetSymbolAddress((void**)&wqh, g_wqh);
    cudaGetSymbolAddress((void**)&wql, g_wql);
    cudaGetSymbolAddress((void**)&wkh, g_wkh);
    cudaGetSymbolAddress((void**)&wkl, g_wkl);
    cudaGetSymbolAddress((void**)&wvh, g_wvh);
    cudaGetSymbolAddress((void**)&wvl, g_wvl);
    cudaGetSymbolAddress((void**)&woh, g_woh);
    cudaGetSymbolAddress((void**)&wol, g_wol);

    cudaFuncSetAttribute(mm_split_kernel,
                         cudaFuncAttributeMaxDynamicSharedMemorySize, MM_SMEM);
    cudaFuncSetAttribute(attn_mma_kernel,
                         cudaFuncAttributeMaxDynamicSharedMemorySize, ATT_SMEM);

    // split x into bf16 hi/lo
    int n4 = MROWS * CC / 4;
    split_kernel<<<(n4 + 255) / 256, 256>>>(x, xh, xl, n4);

    // transpose + split weights
    dim3 tgrid(CC / 32, CC / 32);
    transpose_split_kernel<<<tgrid, 256>>>(wq, wqh, wql);
    transpose_split_kernel<<<tgrid, 256>>>(wk, wkh, wkl);
    transpose_split_kernel<<<tgrid, 256>>>(wv, wvh, wvl);
    transpose_split_kernel<<<tgrid, 256>>>(wo, woh, wol);

    // QKV projections; q scaled by 1/8; epilogue writes bf16 hi/lo directly
    dim3 ggrid(CC / Bb_N, MROWS / Bb_M);   // (6, 64)
    mm_split_kernel<<<ggrid, 256, MM_SMEM>>>(xh, xl, wqh, wql, bq, 0.125f,
                                             nullptr, qh, ql);
    mm_split_kernel<<<ggrid, 256, MM_SMEM>>>(xh, xl, wkh, wkl, bk, 1.0f,
                                             nullptr, kh, kl);
    mm_split_kernel<<<ggrid, 256, MM_SMEM>>>(xh, xl, wvh, wvl, bv, 1.0f,
                                             nullptr, vh, vl);

    // tensor-core flash attention
    dim3 agrid(TT / AQ, HH, BB);           // (16, 12, 8)
    attn_mma_kernel<<<agrid, 128, ATT_SMEM>>>(qh, ql, kh, kl, vh, vl, ah, al);

    // output projection (fp32 out)
    mm_split_kernel<<<ggrid, 256, MM_SMEM>>>(ah, al, woh, wol, bo, 1.0f,
                                             out, nullptr, nullptr);
}